// round 16
// baseline (speedup 1.0000x reference)
#include <cuda_runtime.h>
#include <cuda_bf16.h>
#include <cstdint>

#define TT 2048
#define BB 16
#define DD 1024
#define NN 64
#define MT (TT * BB)      // 32768 rows
#define NC 256            // k|v|q|a packed columns
#define PAD_T 32          // zero padding time-steps (device globals zero-init)
#define CCH 16            // chunk size
#define NCH (TT / CCH)    // 128 chunks

// ------------------------- device scratch (no allocs allowed) ---------------
__device__ float g_proj[(size_t)(MT + PAD_T * BB) * NC];       // + pad (zero)
__device__ float g_gramc[(size_t)(NCH + 2) * BB * 256];        // in-chunk k-Gram (+pad)
__device__ float2 g_ac[(size_t)MT * NN];                       // (alpha, cc)
__device__ float g_Scs[(size_t)NCH * BB * NN * NN];            // chunk-start states
__device__ __nv_bfloat16 g_whi[(size_t)NC * DD];
__device__ __nv_bfloat16 g_wlo[(size_t)NC * DD];

// ---------------------------------------------------------------------------
// Convert W (4 matrices stacked: k|v|q|a) -> bf16 hi/lo
// ---------------------------------------------------------------------------
__global__ __launch_bounds__(256) void convert_w(
    const float* __restrict__ Wk, const float* __restrict__ Wv,
    const float* __restrict__ Wq, const float* __restrict__ Wa)
{
    int e4 = blockIdx.x * 256 + threadIdx.x;
    int base = e4 * 4;
    int row = base >> 10;
    int colk = base & 1023;
    int cb = row >> 6, n = row & 63;
    const float* W = (cb == 0) ? Wk : (cb == 1) ? Wv : (cb == 2) ? Wq : Wa;
    float4 v = *(const float4*)(W + (size_t)n * DD + colk);
    __nv_bfloat16 h0 = __float2bfloat16(v.x);
    __nv_bfloat16 h1 = __float2bfloat16(v.y);
    __nv_bfloat16 h2 = __float2bfloat16(v.z);
    __nv_bfloat16 h3 = __float2bfloat16(v.w);
    __nv_bfloat16 l0 = __float2bfloat16(v.x - __bfloat162float(h0));
    __nv_bfloat16 l1 = __float2bfloat16(v.y - __bfloat162float(h1));
    __nv_bfloat16 l2 = __float2bfloat16(v.z - __bfloat162float(h2));
    __nv_bfloat16 l3 = __float2bfloat16(v.w - __bfloat162float(h3));
    __nv_bfloat162 hp0 = __halves2bfloat162(h0, h1);
    __nv_bfloat162 hp1 = __halves2bfloat162(h2, h3);
    __nv_bfloat162 lp0 = __halves2bfloat162(l0, l1);
    __nv_bfloat162 lp1 = __halves2bfloat162(l2, l3);
    *(uint2*)&g_whi[(size_t)row * DD + colk] = make_uint2(*(uint32_t*)&hp0, *(uint32_t*)&hp1);
    *(uint2*)&g_wlo[(size_t)row * DD + colk] = make_uint2(*(uint32_t*)&lp0, *(uint32_t*)&lp1);
}

// ---------------------------------------------------------------------------
// Fused tensor-core GEMM (R9/R11 winner).
// ---------------------------------------------------------------------------
#define GBM 128
#define GBN 128
#define GBK 32
#define SA  40

#define MMA16816(d, a, b0v, b1v)                                              \
    asm volatile("mma.sync.aligned.m16n8k16.row.col.f32.bf16.bf16.f32 "       \
                 "{%0,%1,%2,%3}, {%4,%5,%6,%7}, {%8,%9}, {%0,%1,%2,%3};"      \
                 : "+f"(d[0]), "+f"(d[1]), "+f"(d[2]), "+f"(d[3])             \
                 : "r"(a[0]), "r"(a[1]), "r"(a[2]), "r"(a[3]),                \
                   "r"(b0v), "r"(b1v));

__device__ __forceinline__ void split4(float4 v, uint32_t& h01, uint32_t& h23,
                                       uint32_t& l01, uint32_t& l23) {
    __nv_bfloat16 h0 = __float2bfloat16(v.x);
    __nv_bfloat16 h1 = __float2bfloat16(v.y);
    __nv_bfloat16 h2 = __float2bfloat16(v.z);
    __nv_bfloat16 h3 = __float2bfloat16(v.w);
    __nv_bfloat16 l0 = __float2bfloat16(v.x - __bfloat162float(h0));
    __nv_bfloat16 l1 = __float2bfloat16(v.y - __bfloat162float(h1));
    __nv_bfloat16 l2 = __float2bfloat16(v.z - __bfloat162float(h2));
    __nv_bfloat16 l3 = __float2bfloat16(v.w - __bfloat162float(h3));
    __nv_bfloat162 hp0 = __halves2bfloat162(h0, h1);
    __nv_bfloat162 hp1 = __halves2bfloat162(h2, h3);
    __nv_bfloat162 lp0 = __halves2bfloat162(l0, l1);
    __nv_bfloat162 lp1 = __halves2bfloat162(l2, l3);
    h01 = *(uint32_t*)&hp0; h23 = *(uint32_t*)&hp1;
    l01 = *(uint32_t*)&lp0; l23 = *(uint32_t*)&lp1;
}

__global__ __launch_bounds__(256) void mma_gemm(const float* __restrict__ x) {
    __shared__ alignas(16) __nv_bfloat16 Ah[GBM * SA];
    __shared__ alignas(16) __nv_bfloat16 Al[GBM * SA];
    __shared__ alignas(16) __nv_bfloat16 Bh[GBN * SA];
    __shared__ alignas(16) __nv_bfloat16 Bl[GBN * SA];

    const int tid = threadIdx.x;
    const int wid = tid >> 5, lane = tid & 31;
    const int wm = wid & 3, wn = wid >> 2;
    const int col0 = blockIdx.x * GBN;
    const int row0 = blockIdx.y * GBM;
    const int g = lane >> 2, tg = lane & 3;

    int ra[4], ca4[4];
#pragma unroll
    for (int l = 0; l < 4; l++) {
        int f = tid + 256 * l;
        ra[l] = f >> 3;
        ca4[l] = (f & 7) << 2;
    }
    int rb[2], kb8[2];
#pragma unroll
    for (int l = 0; l < 2; l++) {
        int f = tid + 256 * l;
        rb[l] = f >> 2;
        kb8[l] = (f & 3) << 3;
    }

    float acc[2][8][4];
#pragma unroll
    for (int a = 0; a < 2; a++)
#pragma unroll
        for (int b = 0; b < 8; b++)
#pragma unroll
            for (int r = 0; r < 4; r++) acc[a][b][r] = 0.f;

    float4 av[4];
    uint4 bhv[2], blv[2];
#pragma unroll
    for (int l = 0; l < 4; l++)
        av[l] = *(const float4*)(x + (size_t)(row0 + ra[l]) * DD + ca4[l]);
#pragma unroll
    for (int l = 0; l < 2; l++) {
        size_t gb = (size_t)(col0 + rb[l]) * DD + kb8[l];
        bhv[l] = *(const uint4*)&g_whi[gb];
        blv[l] = *(const uint4*)&g_wlo[gb];
    }

    for (int kb = 0; kb < DD; kb += GBK) {
#pragma unroll
        for (int l = 0; l < 4; l++) {
            uint32_t h01, h23, l01, l23;
            split4(av[l], h01, h23, l01, l23);
            *(uint2*)&Ah[ra[l] * SA + ca4[l]] = make_uint2(h01, h23);
            *(uint2*)&Al[ra[l] * SA + ca4[l]] = make_uint2(l01, l23);
        }
#pragma unroll
        for (int l = 0; l < 2; l++) {
            *(uint4*)&Bh[rb[l] * SA + kb8[l]] = bhv[l];
            *(uint4*)&Bl[rb[l] * SA + kb8[l]] = blv[l];
        }
        __syncthreads();

        if (kb + GBK < DD) {
#pragma unroll
            for (int l = 0; l < 4; l++)
                av[l] = *(const float4*)(x + (size_t)(row0 + ra[l]) * DD + kb + GBK + ca4[l]);
#pragma unroll
            for (int l = 0; l < 2; l++) {
                size_t gb = (size_t)(col0 + rb[l]) * DD + kb + GBK + kb8[l];
                bhv[l] = *(const uint4*)&g_whi[gb];
                blv[l] = *(const uint4*)&g_wlo[gb];
            }
        }

#pragma unroll
        for (int ks = 0; ks < GBK; ks += 16) {
            uint32_t afh[2][4], afl[2][4];
            const int kk2 = ks + 2 * tg;
#pragma unroll
            for (int ms = 0; ms < 2; ms++) {
                int rr = wm * 32 + ms * 16 + g;
                afh[ms][0] = *(const uint32_t*)&Ah[rr * SA + kk2];
                afh[ms][1] = *(const uint32_t*)&Ah[(rr + 8) * SA + kk2];
                afh[ms][2] = *(const uint32_t*)&Ah[rr * SA + kk2 + 8];
                afh[ms][3] = *(const uint32_t*)&Ah[(rr + 8) * SA + kk2 + 8];
                afl[ms][0] = *(const uint32_t*)&Al[rr * SA + kk2];
                afl[ms][1] = *(const uint32_t*)&Al[(rr + 8) * SA + kk2];
                afl[ms][2] = *(const uint32_t*)&Al[rr * SA + kk2 + 8];
                afl[ms][3] = *(const uint32_t*)&Al[(rr + 8) * SA + kk2 + 8];
            }
#pragma unroll
            for (int ns = 0; ns < 8; ns++) {
                int nr = wn * 64 + ns * 8 + g;
                uint32_t bh0 = *(const uint32_t*)&Bh[nr * SA + kk2];
                uint32_t bh1 = *(const uint32_t*)&Bh[nr * SA + kk2 + 8];
                uint32_t bl0 = *(const uint32_t*)&Bl[nr * SA + kk2];
                uint32_t bl1 = *(const uint32_t*)&Bl[nr * SA + kk2 + 8];
#pragma unroll
                for (int ms = 0; ms < 2; ms++) {
                    MMA16816(acc[ms][ns], afh[ms], bh0, bh1);
                    MMA16816(acc[ms][ns], afh[ms], bl0, bl1);
                    MMA16816(acc[ms][ns], afl[ms], bh0, bh1);
                }
            }
        }
        __syncthreads();
    }

#pragma unroll
    for (int ms = 0; ms < 2; ms++)
#pragma unroll
        for (int ns = 0; ns < 8; ns++) {
            int m = row0 + wm * 32 + ms * 16 + g;
            int n = col0 + wn * 64 + ns * 8 + tg * 2;
            *(float2*)&g_proj[(size_t)m * NC + n] =
                make_float2(acc[ms][ns][0], acc[ms][ns][1]);
            *(float2*)&g_proj[(size_t)(m + 8) * NC + n] =
                make_float2(acc[ms][ns][2], acc[ms][ns][3]);
        }
}

// ---------------------------------------------------------------------------
// In-chunk Gram (R11): G[t*16+u] = k_t . k_u.
// ---------------------------------------------------------------------------
__global__ __launch_bounds__(256) void gramc_kernel() {
    const int b  = blockIdx.x & 15;
    const int ch = blockIdx.x >> 4;
    const int tid = threadIdx.x;
    __shared__ float Ks[16][68];

    {
        const int s = tid >> 4, j4 = (tid & 15) * 4;
        float4 kv = *(const float4*)(g_proj + ((size_t)(ch * CCH + s) * BB + b) * NC + j4);
        *(float4*)&Ks[s][j4] = kv;
    }
    __syncthreads();

    const int t = tid >> 4, u = tid & 15;
    float acc = 0.f;
#pragma unroll
    for (int j = 0; j < 64; j++) acc = fmaf(Ks[t][j], Ks[u][j], acc);
    g_gramc[((size_t)ch * BB + b) * 256 + t * 16 + u] = acc;
}

// ---------------------------------------------------------------------------
// scanA v6 (= R11 + slim serial warp):
//  ph2 (warp 0) stores only (alpha,cc) to smem ACs — suffix pass, Wsbuf and
//  g_ac stores are done by ALL 256 threads after the barrier.
//  Row-local smem deps (Wsbuf, Sbuf) use __syncwarp; 2 block bars/chunk.
// ---------------------------------------------------------------------------
__device__ __forceinline__ float fast_tanh(float x) {
    float r;
    asm("tanh.approx.f32 %0, %1;" : "=f"(r) : "f"(x));
    return r;
}

__global__ __launch_bounds__(256) void scanA_kernel(
    const float* __restrict__ S_in,
    const float* __restrict__ dA,
    const float* __restrict__ bA,
    float* __restrict__ out)
{
    const int b  = blockIdx.x >> 2;
    const int qr = blockIdx.x & 3;
    const int i0 = qr * 16;
    const int tid = threadIdx.x;
    const int il = tid >> 4;          // row in block 0..15
    const int i  = i0 + il;           // global row
    const int c  = tid & 15;          // lane in row
    const int j0 = c * 4;

    __shared__ float Kbuf[2][16 * 68];
    __shared__ float Gbuf[2][256];
    __shared__ float Vbuf[2][16][16];   // [buf][s][row]
    __shared__ float Abuf[2][16][16];
    __shared__ float2 ACs[16][17];      // [row][s] = (alpha, cc)
    __shared__ float Wsbuf[16][20];     // [row][ws0..15, pi]
    __shared__ float Grebuf[16][20];    // [row][d]
    __shared__ float Sbuf[16][68];      // [row][j]

    const int sk = il, jk = j0;
    const int sv = il, iv = c;

    float S0, S1, S2, S3;
    {
        float4 si = *(const float4*)(S_in + ((size_t)b * NN + i) * NN + j0);
        S0 = si.x; S1 = si.y; S2 = si.z; S3 = si.w;
        *(float4*)(g_Scs + ((size_t)b * NN + i) * NN + j0) = si;   // Scs[0]
        *(float4*)&Sbuf[il][j0] = si;
    }
    float dah = 0.f, bah = 0.f;
    if (tid < 16) {
        dah = 0.5f * dA[i0 + tid];
        bah = 0.5f * bA[i0 + tid];
    }

    // ---- prologue: stage chunk 0 tiles into buf 0 ----
    {
        float4 kpre0 = *(const float4*)(g_proj + ((size_t)sk * BB + b) * NC + jk);
        float4 gpre0 = make_float4(0, 0, 0, 0);
        if (tid < 64) gpre0 = *(const float4*)(g_gramc + (size_t)b * 256 + tid * 4);
        float vpre0 = g_proj[((size_t)sv * BB + b) * NC + 64 + i0 + iv];
        float apre0 = g_proj[((size_t)sv * BB + b) * NC + 192 + i0 + iv];
        *(float4*)&Kbuf[0][sk * 68 + jk] = kpre0;
        if (tid < 64) *(float4*)&Gbuf[0][tid * 4] = gpre0;
        Vbuf[0][sv][iv] = vpre0;
        Abuf[0][sv][iv] = apre0;
    }
    __syncthreads();

    // ---- prologue Gre: Gre[il][c] = S_init[il] . k_c (chunk 0) ----
    {
        float acc = 0.f;
#pragma unroll
        for (int j4 = 0; j4 < 64; j4 += 4) {
            float4 sv4 = *(const float4*)&Sbuf[il][j4];
            float4 kv4 = *(const float4*)&Kbuf[0][c * 68 + j4];
            acc = fmaf(sv4.x, kv4.x, acc);
            acc = fmaf(sv4.y, kv4.y, acc);
            acc = fmaf(sv4.z, kv4.z, acc);
            acc = fmaf(sv4.w, kv4.w, acc);
        }
        Grebuf[il][c] = acc;
    }

    // ---- prologue LDG chunk 1 -> regs ----
    float4 kpre, gpre;
    float vpre, apre;
    {
        const size_t tb1 = (size_t)CCH * BB + b;
        kpre = *(const float4*)(g_proj + (tb1 + (size_t)sk * BB) * NC + jk);
        gpre = make_float4(0, 0, 0, 0);
        if (tid < 64)
            gpre = *(const float4*)(g_gramc + ((size_t)1 * BB + b) * 256 + tid * 4);
        vpre = g_proj[(tb1 + (size_t)sv * BB) * NC + 64 + i0 + iv];
        apre = g_proj[(tb1 + (size_t)sv * BB) * NC + 192 + i0 + iv];
    }
    __syncthreads();

    for (int ch = 0; ch < NCH; ch++) {
        const int cb = ch & 1, nb = cb ^ 1;

        // ---- stage regs (chunk ch+1) into buffer nb ----
        *(float4*)&Kbuf[nb][sk * 68 + jk] = kpre;
        if (tid < 64) *(float4*)&Gbuf[nb][tid * 4] = gpre;
        Vbuf[nb][sv][iv] = vpre;
        Abuf[nb][sv][iv] = apre;

        // ---- issue LDGs for chunk ch+2 (pad-safe, PAD_T=32) ----
        {
            const size_t tb2 = (size_t)((ch + 2) * CCH) * BB + b;
            kpre = *(const float4*)(g_proj + (tb2 + (size_t)sk * BB) * NC + jk);
            if (tid < 64)
                gpre = *(const float4*)(g_gramc + ((size_t)(ch + 2) * BB + b) * 256 + tid * 4);
            vpre = g_proj[(tb2 + (size_t)sv * BB) * NC + 64 + i0 + iv];
            apre = g_proj[(tb2 + (size_t)sv * BB) * NC + 192 + i0 + iv];
        }

        // ---- ph2: single-warp register E-ladder (lane = row) ----
        if (tid < 16) {
            const int r = tid;
            float E[16];
#pragma unroll
            for (int d4 = 0; d4 < 16; d4 += 4) {
                float4 f = *(const float4*)&Grebuf[r][d4];
                E[d4] = f.x; E[d4 + 1] = f.y; E[d4 + 2] = f.z; E[d4 + 3] = f.w;
            }
            float alp, ccp;
            {
                float xg = fmaf(dah, E[0], fmaf(0.5f, Abuf[cb][0][r], bah));
                alp = fmaf(0.5f, fast_tanh(xg), 0.5f);
                float v0 = Vbuf[cb][0][r];
                ccp = fmaf(-alp, v0, v0);
                ACs[r][0] = make_float2(alp, ccp);
            }
#pragma unroll
            for (int s = 1; s < 16; s++) {
                float g[16];
#pragma unroll
                for (int u4 = 0; u4 < 16; u4 += 4) {
                    float4 f = *(const float4*)&Gbuf[cb][(s - 1) * 16 + u4];
                    g[u4] = f.x; g[u4 + 1] = f.y; g[u4 + 2] = f.z; g[u4 + 3] = f.w;
                }
#pragma unroll
                for (int d = 15; d >= s; d--)
                    E[d] = fmaf(alp, E[d], ccp * g[d]);
                float xg = fmaf(dah, E[s], fmaf(0.5f, Abuf[cb][s][r], bah));
                float al = fmaf(0.5f, fast_tanh(xg), 0.5f);
                float vv = Vbuf[cb][s][r];
                float cc = fmaf(-al, vv, vv);
                ACs[r][s] = make_float2(al, cc);
                alp = al; ccp = cc;
            }
        }
        __syncthreads();   // ACs + nb staging visible

        // ---- ph3a (all threads): ws from ACs; g_ac store; Wsbuf ----
        {
            float p = 1.f;
#pragma unroll
            for (int t = 1; t < 16; t++)
                if (t > c) p *= ACs[il][t].x;
            float2 acc_ = ACs[il][c];
            Wsbuf[il][c] = acc_.y * p;
            if (c == 0) Wsbuf[il][16] = p * acc_.x;
            g_ac[((size_t)(ch * CCH + c) * BB + b) * NN + i0 + il] = acc_;
        }
        __syncwarp();      // Wsbuf row-local (16 contiguous lanes)

        // ---- ph3b: S rank-16 update; write Sbuf + Scs/out ----
        {
            float pi2 = Wsbuf[il][16];
            float n0 = pi2 * S0, n1 = pi2 * S1, n2 = pi2 * S2, n3 = pi2 * S3;
#pragma unroll
            for (int s = 0; s < 16; s++) {
                float w = Wsbuf[il][s];
                float4 k4 = *(const float4*)&Kbuf[cb][s * 68 + j0];
                n0 = fmaf(w, k4.x, n0);
                n1 = fmaf(w, k4.y, n1);
                n2 = fmaf(w, k4.z, n2);
                n3 = fmaf(w, k4.w, n3);
            }
            S0 = n0; S1 = n1; S2 = n2; S3 = n3;
            float4 sv4 = make_float4(S0, S1, S2, S3);
            *(float4*)&Sbuf[il][j0] = sv4;
            if (ch < NCH - 1)
                *(float4*)(g_Scs + (size_t)(ch + 1) * BB * NN * NN
                           + ((size_t)b * NN + i) * NN + j0) = sv4;
            else
                *(float4*)(out + (size_t)TT * BB * NN
                           + ((size_t)b * NN + i) * NN + j0) = sv4;
        }
        __syncwarp();      // Sbuf row-local

        // ---- ph3c: Gre[il][c] = Sbuf[il] . Knext[c] ----
        {
            float acc = 0.f;
#pragma unroll
            for (int j4 = 0; j4 < 64; j4 += 4) {
                float4 sv4 = *(const float4*)&Sbuf[il][j4];
                float4 kv4 = *(const float4*)&Kbuf[nb][c * 68 + j4];
                acc = fmaf(sv4.x, kv4.x, acc);
                acc = fmaf(sv4.y, kv4.y, acc);
                acc = fmaf(sv4.z, kv4.z, acc);
                acc = fmaf(sv4.w, kv4.w, acc);
            }
            Grebuf[il][c] = acc;
        }
        __syncthreads();   // Grebuf visible to ph2; Kbuf[cb] free for restage
    }
}

// ---------------------------------------------------------------------------
// b3: outputs (R11). Block per (b,chunk), 64 threads (thread = row i).
// ---------------------------------------------------------------------------
__global__ __launch_bounds__(64) void b3_out(float* __restrict__ out) {
    const int b  = blockIdx.x & 15;
    const int ch = blockIdx.x >> 4;
    const int tid = threadIdx.x;          // = i

    __shared__ float Ks[CCH][68];
    __shared__ float Qs[CCH][68];
    __shared__ float Dm[CCH][CCH];

#pragma unroll
    for (int s = 0; s < CCH; s++) {
        const float* P = g_proj + ((size_t)(ch * CCH + s) * BB + b) * NC;
        Ks[s][tid] = P[tid];
        Qs[s][tid] = P[128 + tid];
    }
    __syncthreads();

#pragma unroll
    for (int e = 0; e < 4; e++) {
        int id = tid * 4 + e;
        int s = id >> 4, t = id & 15;
        float a = 0.f;
#pragma unroll
        for (int j = 0; j < NN; j++) a = fmaf(Ks[s][j], Qs[t][j], a);
        Dm[s][t] = a;
    }
    __syncthreads();

    float Sr[NN];
    {
        const float* P = g_Scs + (size_t)ch * BB * NN * NN + ((size_t)b * NN + tid) * NN;
#pragma unroll
        for (int j = 0; j < NN; j += 4) {
            float4 f = *(const float4*)(P + j);
            Sr[j] = f.x; Sr[j + 1] = f.y; Sr[j + 2] = f.z; Sr[j + 3] = f.w;
        }
    }

    float gt[CCH];
#pragma unroll
    for (int t = 0; t < CCH; t++) {
        float a = 0.f;
#pragma unroll
        for (int j = 0; j < NN; j++) a = fmaf(Sr[j], Qs[t][j], a);
        gt[t] = a;
    }

    float al[CCH], cc[CCH];
#pragma unroll
    for (int s = 0; s < CCH; s++) {
        float2 v = g_ac[((size_t)(ch * CCH + s) * BB + b) * NN + tid];
        al[s] = v.x; cc[s] = v.y;
    }

    float w[CCH];
    float pi = 1.f;
#pragma unroll
    for (int t = 0; t < CCH; t++) {
        float a = al[t];
        pi *= a;
#pragma unroll
        for (int s = 0; s < CCH; s++)
            if (s < t) w[s] *= a;
        w[t] = cc[t];
        float o = pi * gt[t];
#pragma unroll
        for (int s = 0; s < CCH; s++)
            if (s <= t) o = fmaf(w[s], Dm[s][t], o);
        float sg = fmaf(0.5f, fast_tanh(0.5f * o), 0.5f);
        out[((size_t)(ch * CCH + t) * BB + b) * NN + tid] = o * o * sg;
    }
}

extern "C" void kernel_launch(void* const* d_in, const int* in_sizes, int n_in,
                              void* d_out, int out_size) {
    const float* x  = (const float*)d_in[0];
    const float* S  = (const float*)d_in[1];
    const float* Wk = (const float*)d_in[2];
    const float* Wv = (const float*)d_in[3];
    const float* Wq = (const float*)d_in[4];
    const float* Wa = (const float*)d_in[5];
    const float* da = (const float*)d_in[6];
    const float* ba = (const float*)d_in[7];
    float* out = (float*)d_out;

    convert_w<<<NC * DD / (256 * 4), 256>>>(Wk, Wv, Wq, Wa);
    dim3 ggrid(NC / GBN, MT / GBM);
    mma_gemm<<<ggrid, 256>>>(x);
    gramc_kernel<<<NCH * BB, 256>>>();
    scanA_kernel<<<BB * 4, 256>>>(S, da, ba, out);
    b3_out<<<NCH * BB, 64>>>(out);
}

// round 17
// speedup vs baseline: 1.1132x; 1.1132x over previous
#include <cuda_runtime.h>
#include <cuda_bf16.h>
#include <cstdint>

#define TT 2048
#define BB 16
#define DD 1024
#define NN 64
#define MT (TT * BB)      // 32768 rows
#define NC 256            // k|v|q|a packed columns
#define PAD_T 32          // zero padding time-steps (device globals zero-init)
#define CCH 16            // chunk size
#define NCH (TT / CCH)    // 128 chunks

// ------------------------- device scratch (no allocs allowed) ---------------
__device__ float g_proj[(size_t)(MT + PAD_T * BB) * NC];       // + pad (zero)
__device__ float g_gramc[(size_t)(NCH + 2) * BB * 512];        // [self 256 | cross 256]
__device__ float2 g_ac[(size_t)MT * NN];                       // (alpha, cc)
__device__ float g_Scs[(size_t)NCH * BB * NN * NN];            // chunk-start states
__device__ __nv_bfloat16 g_whi[(size_t)NC * DD];
__device__ __nv_bfloat16 g_wlo[(size_t)NC * DD];

// ---------------------------------------------------------------------------
// Convert W (4 matrices stacked: k|v|q|a) -> bf16 hi/lo
// ---------------------------------------------------------------------------
__global__ __launch_bounds__(256) void convert_w(
    const float* __restrict__ Wk, const float* __restrict__ Wv,
    const float* __restrict__ Wq, const float* __restrict__ Wa)
{
    int e4 = blockIdx.x * 256 + threadIdx.x;
    int base = e4 * 4;
    int row = base >> 10;
    int colk = base & 1023;
    int cb = row >> 6, n = row & 63;
    const float* W = (cb == 0) ? Wk : (cb == 1) ? Wv : (cb == 2) ? Wq : Wa;
    float4 v = *(const float4*)(W + (size_t)n * DD + colk);
    __nv_bfloat16 h0 = __float2bfloat16(v.x);
    __nv_bfloat16 h1 = __float2bfloat16(v.y);
    __nv_bfloat16 h2 = __float2bfloat16(v.z);
    __nv_bfloat16 h3 = __float2bfloat16(v.w);
    __nv_bfloat16 l0 = __float2bfloat16(v.x - __bfloat162float(h0));
    __nv_bfloat16 l1 = __float2bfloat16(v.y - __bfloat162float(h1));
    __nv_bfloat16 l2 = __float2bfloat16(v.z - __bfloat162float(h2));
    __nv_bfloat16 l3 = __float2bfloat16(v.w - __bfloat162float(h3));
    __nv_bfloat162 hp0 = __halves2bfloat162(h0, h1);
    __nv_bfloat162 hp1 = __halves2bfloat162(h2, h3);
    __nv_bfloat162 lp0 = __halves2bfloat162(l0, l1);
    __nv_bfloat162 lp1 = __halves2bfloat162(l2, l3);
    *(uint2*)&g_whi[(size_t)row * DD + colk] = make_uint2(*(uint32_t*)&hp0, *(uint32_t*)&hp1);
    *(uint2*)&g_wlo[(size_t)row * DD + colk] = make_uint2(*(uint32_t*)&lp0, *(uint32_t*)&lp1);
}

// ---------------------------------------------------------------------------
// Fused tensor-core GEMM (R9/R11 winner).
// ---------------------------------------------------------------------------
#define GBM 128
#define GBN 128
#define GBK 32
#define SA  40

#define MMA16816(d, a, b0v, b1v)                                              \
    asm volatile("mma.sync.aligned.m16n8k16.row.col.f32.bf16.bf16.f32 "       \
                 "{%0,%1,%2,%3}, {%4,%5,%6,%7}, {%8,%9}, {%0,%1,%2,%3};"      \
                 : "+f"(d[0]), "+f"(d[1]), "+f"(d[2]), "+f"(d[3])             \
                 : "r"(a[0]), "r"(a[1]), "r"(a[2]), "r"(a[3]),                \
                   "r"(b0v), "r"(b1v));

__device__ __forceinline__ void split4(float4 v, uint32_t& h01, uint32_t& h23,
                                       uint32_t& l01, uint32_t& l23) {
    __nv_bfloat16 h0 = __float2bfloat16(v.x);
    __nv_bfloat16 h1 = __float2bfloat16(v.y);
    __nv_bfloat16 h2 = __float2bfloat16(v.z);
    __nv_bfloat16 h3 = __float2bfloat16(v.w);
    __nv_bfloat16 l0 = __float2bfloat16(v.x - __bfloat162float(h0));
    __nv_bfloat16 l1 = __float2bfloat16(v.y - __bfloat162float(h1));
    __nv_bfloat16 l2 = __float2bfloat16(v.z - __bfloat162float(h2));
    __nv_bfloat16 l3 = __float2bfloat16(v.w - __bfloat162float(h3));
    __nv_bfloat162 hp0 = __halves2bfloat162(h0, h1);
    __nv_bfloat162 hp1 = __halves2bfloat162(h2, h3);
    __nv_bfloat162 lp0 = __halves2bfloat162(l0, l1);
    __nv_bfloat162 lp1 = __halves2bfloat162(l2, l3);
    h01 = *(uint32_t*)&hp0; h23 = *(uint32_t*)&hp1;
    l01 = *(uint32_t*)&lp0; l23 = *(uint32_t*)&lp1;
}

__global__ __launch_bounds__(256) void mma_gemm(const float* __restrict__ x) {
    __shared__ alignas(16) __nv_bfloat16 Ah[GBM * SA];
    __shared__ alignas(16) __nv_bfloat16 Al[GBM * SA];
    __shared__ alignas(16) __nv_bfloat16 Bh[GBN * SA];
    __shared__ alignas(16) __nv_bfloat16 Bl[GBN * SA];

    const int tid = threadIdx.x;
    const int wid = tid >> 5, lane = tid & 31;
    const int wm = wid & 3, wn = wid >> 2;
    const int col0 = blockIdx.x * GBN;
    const int row0 = blockIdx.y * GBM;
    const int g = lane >> 2, tg = lane & 3;

    int ra[4], ca4[4];
#pragma unroll
    for (int l = 0; l < 4; l++) {
        int f = tid + 256 * l;
        ra[l] = f >> 3;
        ca4[l] = (f & 7) << 2;
    }
    int rb[2], kb8[2];
#pragma unroll
    for (int l = 0; l < 2; l++) {
        int f = tid + 256 * l;
        rb[l] = f >> 2;
        kb8[l] = (f & 3) << 3;
    }

    float acc[2][8][4];
#pragma unroll
    for (int a = 0; a < 2; a++)
#pragma unroll
        for (int b = 0; b < 8; b++)
#pragma unroll
            for (int r = 0; r < 4; r++) acc[a][b][r] = 0.f;

    float4 av[4];
    uint4 bhv[2], blv[2];
#pragma unroll
    for (int l = 0; l < 4; l++)
        av[l] = *(const float4*)(x + (size_t)(row0 + ra[l]) * DD + ca4[l]);
#pragma unroll
    for (int l = 0; l < 2; l++) {
        size_t gb = (size_t)(col0 + rb[l]) * DD + kb8[l];
        bhv[l] = *(const uint4*)&g_whi[gb];
        blv[l] = *(const uint4*)&g_wlo[gb];
    }

    for (int kb = 0; kb < DD; kb += GBK) {
#pragma unroll
        for (int l = 0; l < 4; l++) {
            uint32_t h01, h23, l01, l23;
            split4(av[l], h01, h23, l01, l23);
            *(uint2*)&Ah[ra[l] * SA + ca4[l]] = make_uint2(h01, h23);
            *(uint2*)&Al[ra[l] * SA + ca4[l]] = make_uint2(l01, l23);
        }
#pragma unroll
        for (int l = 0; l < 2; l++) {
            *(uint4*)&Bh[rb[l] * SA + kb8[l]] = bhv[l];
            *(uint4*)&Bl[rb[l] * SA + kb8[l]] = blv[l];
        }
        __syncthreads();

        if (kb + GBK < DD) {
#pragma unroll
            for (int l = 0; l < 4; l++)
                av[l] = *(const float4*)(x + (size_t)(row0 + ra[l]) * DD + kb + GBK + ca4[l]);
#pragma unroll
            for (int l = 0; l < 2; l++) {
                size_t gb = (size_t)(col0 + rb[l]) * DD + kb + GBK + kb8[l];
                bhv[l] = *(const uint4*)&g_whi[gb];
                blv[l] = *(const uint4*)&g_wlo[gb];
            }
        }

#pragma unroll
        for (int ks = 0; ks < GBK; ks += 16) {
            uint32_t afh[2][4], afl[2][4];
            const int kk2 = ks + 2 * tg;
#pragma unroll
            for (int ms = 0; ms < 2; ms++) {
                int rr = wm * 32 + ms * 16 + g;
                afh[ms][0] = *(const uint32_t*)&Ah[rr * SA + kk2];
                afh[ms][1] = *(const uint32_t*)&Ah[(rr + 8) * SA + kk2];
                afh[ms][2] = *(const uint32_t*)&Ah[rr * SA + kk2 + 8];
                afh[ms][3] = *(const uint32_t*)&Ah[(rr + 8) * SA + kk2 + 8];
                afl[ms][0] = *(const uint32_t*)&Al[rr * SA + kk2];
                afl[ms][1] = *(const uint32_t*)&Al[(rr + 8) * SA + kk2];
                afl[ms][2] = *(const uint32_t*)&Al[rr * SA + kk2 + 8];
                afl[ms][3] = *(const uint32_t*)&Al[(rr + 8) * SA + kk2 + 8];
            }
#pragma unroll
            for (int ns = 0; ns < 8; ns++) {
                int nr = wn * 64 + ns * 8 + g;
                uint32_t bh0 = *(const uint32_t*)&Bh[nr * SA + kk2];
                uint32_t bh1 = *(const uint32_t*)&Bh[nr * SA + kk2 + 8];
                uint32_t bl0 = *(const uint32_t*)&Bl[nr * SA + kk2];
                uint32_t bl1 = *(const uint32_t*)&Bl[nr * SA + kk2 + 8];
#pragma unroll
                for (int ms = 0; ms < 2; ms++) {
                    MMA16816(acc[ms][ns], afh[ms], bh0, bh1);
                    MMA16816(acc[ms][ns], afh[ms], bl0, bl1);
                    MMA16816(acc[ms][ns], afl[ms], bh0, bh1);
                }
            }
        }
        __syncthreads();
    }

#pragma unroll
    for (int ms = 0; ms < 2; ms++)
#pragma unroll
        for (int ns = 0; ns < 8; ns++) {
            int m = row0 + wm * 32 + ms * 16 + g;
            int n = col0 + wn * 64 + ns * 8 + tg * 2;
            *(float2*)&g_proj[(size_t)m * NC + n] =
                make_float2(acc[ms][ns][0], acc[ms][ns][1]);
            *(float2*)&g_proj[(size_t)(m + 8) * NC + n] =
                make_float2(acc[ms][ns][2], acc[ms][ns][3]);
        }
}

// ---------------------------------------------------------------------------
// Gram kernel: per (ch,b) writes [self 256 | cross 256]:
//   self[t][u]  = k_t^{ch} . k_u^{ch}
//   cross[t][u] = k_t^{ch} . k_u^{ch+1}   (pad beyond T is zero)
// ---------------------------------------------------------------------------
__global__ __launch_bounds__(256) void gramc_kernel() {
    const int b  = blockIdx.x & 15;
    const int ch = blockIdx.x >> 4;
    const int tid = threadIdx.x;
    __shared__ float Ks[16][68];
    __shared__ float Kn[16][68];

    {
        const int s = tid >> 4, j4 = (tid & 15) * 4;
        *(float4*)&Ks[s][j4] =
            *(const float4*)(g_proj + ((size_t)(ch * CCH + s) * BB + b) * NC + j4);
        *(float4*)&Kn[s][j4] =
            *(const float4*)(g_proj + ((size_t)((ch + 1) * CCH + s) * BB + b) * NC + j4);
    }
    __syncthreads();

    const int t = tid >> 4, u = tid & 15;
    float as = 0.f, ac = 0.f;
#pragma unroll
    for (int j = 0; j < 64; j++) {
        as = fmaf(Ks[t][j], Ks[u][j], as);
        ac = fmaf(Ks[t][j], Kn[u][j], ac);
    }
    float* G = g_gramc + ((size_t)ch * BB + b) * 512;
    G[t * 16 + u] = as;
    G[256 + t * 16 + u] = ac;
}

// ---------------------------------------------------------------------------
// scanA v7: warp-specialized chunk pipeline.
//  warp 0: ph2 (R11-verbatim E-ladder + suffix + Wsbuf + g_ac).
//  warps 1-7 (concurrently): stage chunk ch+1 tiles, LDG chunk ch+2,
//    bar.sync(1,224), then X[i][d] = S_{ch-1}[i] . k_d^{(ch+1)}.
//  After one block barrier: ph3 Gre' = pi*X + ws.CG (16 FMA) + ph3b (R11).
//  2 block barriers per chunk.
// ---------------------------------------------------------------------------
__device__ __forceinline__ float fast_tanh(float x) {
    float r;
    asm("tanh.approx.f32 %0, %1;" : "=f"(r) : "f"(x));
    return r;
}

__global__ __launch_bounds__(256) void scanA_kernel(
    const float* __restrict__ S_in,
    const float* __restrict__ dA,
    const float* __restrict__ bA,
    float* __restrict__ out)
{
    const int b  = blockIdx.x >> 2;
    const int qr = blockIdx.x & 3;
    const int i0 = qr * 16;
    const int tid = threadIdx.x;
    const int wid = tid >> 5;
    const int il = tid >> 4;          // row in block 0..15
    const int i  = i0 + il;           // global row
    const int c  = tid & 15;          // lane in row
    const int j0 = c * 4;

    __shared__ float Kbuf[2][16 * 68];
    __shared__ float Gbuf[2][512];      // [self 256 | cross 256]
    __shared__ float Vbuf[2][16][16];   // [buf][s][row]
    __shared__ float Abuf[2][16][16];
    __shared__ float Wsbuf[16][20];     // [row][ws0..15, pi]
    __shared__ float Grebuf[16][20];    // [row][d]
    __shared__ float Xbuf[16][20];      // [row][d] = S_prev . k_d^{next}
    __shared__ float Sbuf[16][68];      // [row][j]

    float S0, S1, S2, S3;
    {
        float4 si = *(const float4*)(S_in + ((size_t)b * NN + i) * NN + j0);
        S0 = si.x; S1 = si.y; S2 = si.z; S3 = si.w;
        *(float4*)(g_Scs + ((size_t)b * NN + i) * NN + j0) = si;   // Scs[0]
        *(float4*)&Sbuf[il][j0] = si;
    }
    float dah = 0.f, bah = 0.f;
    if (tid < 16) {
        dah = 0.5f * dA[i0 + tid];
        bah = 0.5f * bA[i0 + tid];
    }

    // ---- prologue: stage chunk-0 group into buf 0 (all threads) ----
    {
        const int s = tid >> 4, r = tid & 15, c4 = r * 4;
        const float* P = g_proj + ((size_t)s * BB + b) * NC;
        *(float4*)&Kbuf[0][s * 68 + c4] = *(const float4*)(P + c4);
        Vbuf[0][s][r] = P[64 + i0 + r];
        Abuf[0][s][r] = P[192 + i0 + r];
        if (tid < 128)
            *(float4*)&Gbuf[0][tid * 4] =
                *(const float4*)(g_gramc + (size_t)b * 512 + tid * 4);
    }
    __syncthreads();

    // ---- prologue Gre(0): direct dots ----
    {
        float acc = 0.f;
#pragma unroll
        for (int j4 = 0; j4 < 64; j4 += 4) {
            float4 sv4 = *(const float4*)&Sbuf[il][j4];
            float4 kv4 = *(const float4*)&Kbuf[0][c * 68 + j4];
            acc = fmaf(sv4.x, kv4.x, acc);
            acc = fmaf(sv4.y, kv4.y, acc);
            acc = fmaf(sv4.z, kv4.z, acc);
            acc = fmaf(sv4.w, kv4.w, acc);
        }
        Grebuf[il][c] = acc;
    }

    // ---- prologue LDG chunk-1 group into warps 1-7 regs ----
    float4 kpreA = make_float4(0, 0, 0, 0), kpreB = make_float4(0, 0, 0, 0);
    float4 gpre = make_float4(0, 0, 0, 0);
    float vpreA = 0.f, apreA = 0.f, vpreB = 0.f, apreB = 0.f;

    auto ldgroup = [&](int t) {
        const size_t rbase = (size_t)(t * CCH) * BB + b;
        if (tid >= 32) {
            const int e = tid - 32, s = e >> 4, r = e & 15;
            const float* P = g_proj + (rbase + (size_t)s * BB) * NC;
            kpreA = *(const float4*)(P + r * 4);
            vpreA = P[64 + i0 + r];
            apreA = P[192 + i0 + r];
            if (tid < 64) {
                const int e2 = tid + 192, s2 = e2 >> 4, r2 = e2 & 15;
                const float* P2 = g_proj + (rbase + (size_t)s2 * BB) * NC;
                kpreB = *(const float4*)(P2 + r2 * 4);
                vpreB = P2[64 + i0 + r2];
                apreB = P2[192 + i0 + r2];
            }
            if (tid < 160)
                gpre = *(const float4*)(g_gramc + ((size_t)t * BB + b) * 512
                                        + (size_t)(tid - 32) * 4);
        }
    };
    ldgroup(1);
    __syncthreads();   // Grebuf(0) visible to warp 0

    for (int ch = 0; ch < NCH; ch++) {
        const int cb = ch & 1, nb = cb ^ 1;

        if (wid == 0) {
            // ---- ph2 (R11 verbatim): lane = row ----
            if (tid < 16) {
                const int r = tid;
                float E[16];
#pragma unroll
                for (int d4 = 0; d4 < 16; d4 += 4) {
                    float4 f = *(const float4*)&Grebuf[r][d4];
                    E[d4] = f.x; E[d4 + 1] = f.y; E[d4 + 2] = f.z; E[d4 + 3] = f.w;
                }
                float alv[16], cvv[16];
                float alp, ccp;
                {
                    float xg = fmaf(dah, E[0], fmaf(0.5f, Abuf[cb][0][r], bah));
                    alp = fmaf(0.5f, fast_tanh(xg), 0.5f);
                    float v0 = Vbuf[cb][0][r];
                    ccp = fmaf(-alp, v0, v0);
                    alv[0] = alp; cvv[0] = ccp;
                }
#pragma unroll
                for (int s = 1; s < 16; s++) {
                    float g[16];
#pragma unroll
                    for (int u4 = 0; u4 < 16; u4 += 4) {
                        float4 f = *(const float4*)&Gbuf[cb][(s - 1) * 16 + u4];
                        g[u4] = f.x; g[u4 + 1] = f.y; g[u4 + 2] = f.z; g[u4 + 3] = f.w;
                    }
#pragma unroll
                    for (int d = 15; d >= s; d--)
                        E[d] = fmaf(alp, E[d], ccp * g[d]);
                    float xg = fmaf(dah, E[s], fmaf(0.5f, Abuf[cb][s][r], bah));
                    float al = fmaf(0.5f, fast_tanh(xg), 0.5f);
                    float vv = Vbuf[cb][s][r];
                    float cc = fmaf(-al, vv, vv);
                    alv[s] = al; cvv[s] = cc;
                    alp = al; ccp = cc;
                }
                float ws[16];
                float suf = 1.f;
#pragma unroll
                for (int u = 15; u >= 0; u--) {
                    ws[u] = cvv[u] * suf;
                    suf *= alv[u];
                }
#pragma unroll
                for (int u4 = 0; u4 < 16; u4 += 4)
                    *(float4*)&Wsbuf[r][u4] =
                        make_float4(ws[u4], ws[u4 + 1], ws[u4 + 2], ws[u4 + 3]);
                Wsbuf[r][16] = suf;
                float2* acp = g_ac + ((size_t)(ch * CCH) * BB + b) * NN + i0 + r;
#pragma unroll
                for (int s2 = 0; s2 < 16; s2++)
                    acp[(size_t)s2 * BB * NN] = make_float2(alv[s2], cvv[s2]);
            }
        } else {
            // ---- STS staged regs (chunk ch+1 group) into buffer nb ----
            {
                const int e = tid - 32, s = e >> 4, r = e & 15;
                *(float4*)&Kbuf[nb][s * 68 + r * 4] = kpreA;
                Vbuf[nb][s][r] = vpreA;
                Abuf[nb][s][r] = apreA;
                if (tid < 64) {
                    const int e2 = tid + 192, s2 = e2 >> 4, r2 = e2 & 15;
                    *(float4*)&Kbuf[nb][s2 * 68 + r2 * 4] = kpreB;
                    Vbuf[nb][s2][r2] = vpreB;
                    Abuf[nb][s2][r2] = apreB;
                }
                if (tid < 160)
                    *(float4*)&Gbuf[nb][(tid - 32) * 4] = gpre;
            }
            // ---- LDG chunk ch+2 group ----
            ldgroup(ch + 2);
            asm volatile("bar.sync 1, 224;" ::: "memory");
            // ---- X[e>>4][e&15] = Sbuf . k^{(ch+1)} ----
            {
                const int e = tid - 32;
                const int xi = e >> 4, xd = e & 15;
                float acc = 0.f;
#pragma unroll
                for (int j4 = 0; j4 < 64; j4 += 4) {
                    float4 sv4 = *(const float4*)&Sbuf[xi][j4];
                    float4 kv4 = *(const float4*)&Kbuf[nb][xd * 68 + j4];
                    acc = fmaf(sv4.x, kv4.x, acc);
                    acc = fmaf(sv4.y, kv4.y, acc);
                    acc = fmaf(sv4.z, kv4.z, acc);
                    acc = fmaf(sv4.w, kv4.w, acc);
                }
                Xbuf[xi][xd] = acc;
                if (tid < 64) {
                    const int e2 = tid + 192;
                    const int xi2 = e2 >> 4, xd2 = e2 & 15;
                    float acc2 = 0.f;
#pragma unroll
                    for (int j4 = 0; j4 < 64; j4 += 4) {
                        float4 sv4 = *(const float4*)&Sbuf[xi2][j4];
                        float4 kv4 = *(const float4*)&Kbuf[nb][xd2 * 68 + j4];
                        acc2 = fmaf(sv4.x, kv4.x, acc2);
                        acc2 = fmaf(sv4.y, kv4.y, acc2);
                        acc2 = fmaf(sv4.z, kv4.z, acc2);
                        acc2 = fmaf(sv4.w, kv4.w, acc2);
                    }
                    Xbuf[xi2][xd2] = acc2;
                }
            }
        }
        __syncthreads();   // Wsbuf + Xbuf + nb staging visible

        // ---- ph3: Gre' = pi*X + ws.CG (16 FMA per thread) ----
        {
            float pi = Wsbuf[il][16];
            float gre = pi * Xbuf[il][c];
#pragma unroll
            for (int s = 0; s < 16; s++)
                gre = fmaf(Wsbuf[il][s], Gbuf[cb][256 + s * 16 + c], gre);
            Grebuf[il][c] = gre;
        }

        // ---- ph3b (R11 verbatim): S rank-16 update; Sbuf + Scs/out ----
        {
            float pi2 = Wsbuf[il][16];
            float n0 = pi2 * S0, n1 = pi2 * S1, n2 = pi2 * S2, n3 = pi2 * S3;
#pragma unroll
            for (int s = 0; s < 16; s++) {
                float w = Wsbuf[il][s];
                float4 k4 = *(const float4*)&Kbuf[cb][s * 68 + j0];
                n0 = fmaf(w, k4.x, n0);
                n1 = fmaf(w, k4.y, n1);
                n2 = fmaf(w, k4.z, n2);
                n3 = fmaf(w, k4.w, n3);
            }
            S0 = n0; S1 = n1; S2 = n2; S3 = n3;
            float4 sv4 = make_float4(S0, S1, S2, S3);
            *(float4*)&Sbuf[il][j0] = sv4;
            if (ch < NCH - 1)
                *(float4*)(g_Scs + (size_t)(ch + 1) * BB * NN * NN
                           + ((size_t)b * NN + i) * NN + j0) = sv4;
            else
                *(float4*)(out + (size_t)TT * BB * NN
                           + ((size_t)b * NN + i) * NN + j0) = sv4;
        }
        __syncthreads();   // Grebuf + Sbuf visible for next iteration
    }
}

// ---------------------------------------------------------------------------
// b3: outputs (R11). Block per (b,chunk), 64 threads (thread = row i).
// ---------------------------------------------------------------------------
__global__ __launch_bounds__(64) void b3_out(float* __restrict__ out) {
    const int b  = blockIdx.x & 15;
    const int ch = blockIdx.x >> 4;
    const int tid = threadIdx.x;          // = i

    __shared__ float Ks[CCH][68];
    __shared__ float Qs[CCH][68];
    __shared__ float Dm[CCH][CCH];

#pragma unroll
    for (int s = 0; s < CCH; s++) {
        const float* P = g_proj + ((size_t)(ch * CCH + s) * BB + b) * NC;
        Ks[s][tid] = P[tid];
        Qs[s][tid] = P[128 + tid];
    }
    __syncthreads();

#pragma unroll
    for (int e = 0; e < 4; e++) {
        int id = tid * 4 + e;
        int s = id >> 4, t = id & 15;
        float a = 0.f;
#pragma unroll
        for (int j = 0; j < NN; j++) a = fmaf(Ks[s][j], Qs[t][j], a);
        Dm[s][t] = a;
    }
    __syncthreads();

    float Sr[NN];
    {
        const float* P = g_Scs + (size_t)ch * BB * NN * NN + ((size_t)b * NN + tid) * NN;
#pragma unroll
        for (int j = 0; j < NN; j += 4) {
            float4 f = *(const float4*)(P + j);
            Sr[j] = f.x; Sr[j + 1] = f.y; Sr[j + 2] = f.z; Sr[j + 3] = f.w;
        }
    }

    float gt[CCH];
#pragma unroll
    for (int t = 0; t < CCH; t++) {
        float a = 0.f;
#pragma unroll
        for (int j = 0; j < NN; j++) a = fmaf(Sr[j], Qs[t][j], a);
        gt[t] = a;
    }

    float al[CCH], cc[CCH];
#pragma unroll
    for (int s = 0; s < CCH; s++) {
        float2 v = g_ac[((size_t)(ch * CCH + s) * BB + b) * NN + tid];
        al[s] = v.x; cc[s] = v.y;
    }

    float w[CCH];
    float pi = 1.f;
#pragma unroll
    for (int t = 0; t < CCH; t++) {
        float a = al[t];
        pi *= a;
#pragma unroll
        for (int s = 0; s < CCH; s++)
            if (s < t) w[s] *= a;
        w[t] = cc[t];
        float o = pi * gt[t];
#pragma unroll
        for (int s = 0; s < CCH; s++)
            if (s <= t) o = fmaf(w[s], Dm[s][t], o);
        float sg = fmaf(0.5f, fast_tanh(0.5f * o), 0.5f);
        out[((size_t)(ch * CCH + t) * BB + b) * NN + tid] = o * o * sg;
    }
}

extern "C" void kernel_launch(void* const* d_in, const int* in_sizes, int n_in,
                              void* d_out, int out_size) {
    const float* x  = (const float*)d_in[0];
    const float* S  = (const float*)d_in[1];
    const float* Wk = (const float*)d_in[2];
    const float* Wv = (const float*)d_in[3];
    const float* Wq = (const float*)d_in[4];
    const float* Wa = (const float*)d_in[5];
    const float* da = (const float*)d_in[6];
    const float* ba = (const float*)d_in[7];
    float* out = (float*)d_out;

    convert_w<<<NC * DD / (256 * 4), 256>>>(Wk, Wv, Wq, Wa);
    dim3 ggrid(NC / GBN, MT / GBM);
    mma_gemm<<<ggrid, 256>>>(x);
    gramc_kernel<<<NCH * BB, 256>>>();
    scanA_kernel<<<BB * 4, 256>>>(S, da, ba, out);
    b3_out<<<NCH * BB, 64>>>(out);
}